// round 16
// baseline (speedup 1.0000x reference)
#include <cuda_runtime.h>
#include <cuda_fp16.h>
#include <mma.h>
#include <math.h>

using namespace nvcuda;

#define NN 100000
#define EE 1600000
#define GG 32
#define INC 100
#define HC 64
#define EPS 1e-5f
#define NBLK 98            // ceil(NN/1024)
#define FPS 1048576.0f     // 2^20 fixed-point scale for degree

// ---------------- scratch (zero-initialized at module load; kernels that
// consume one-shot state re-zero it afterwards so graph replays are exact) ----
__device__ unsigned long long g_packed[NN];  // (count<<32) | fixedpoint(sum|w|)
__device__ float  g_dinv [NN];
__device__ int    g_cnt_e[NN];
__device__ int    g_rowst[NN];
__device__ int    g_bsum [128];
__device__ int    g_pos  [EE];
__device__ unsigned long long g_csr[EE];     // packed (|ew| bits << 32) | src
__device__ __half g_bufH [(size_t)NN * HC];  // GEMM output (dinv-scaled before prop)
__device__ __half g_bufB [(size_t)NN * HC];  // prop output (next GEMM input)
__device__ float  g_pool [GG * HC];
__device__ float  g_gcnt [GG];

// streams/events for forked graph capture — created once at load time,
// before any harness memory checkpoint; reused every call (no per-call churn)
static struct GraphStreams {
    cudaStream_t s1;
    cudaEvent_t evRoot, evOff, evGemm;
    GraphStreams() {
        cudaStreamCreateWithFlags(&s1, cudaStreamNonBlocking);
        cudaEventCreateWithFlags(&evRoot, cudaEventDisableTiming);
        cudaEventCreateWithFlags(&evOff,  cudaEventDisableTiming);
        cudaEventCreateWithFlags(&evGemm, cudaEventDisableTiming);
    }
} g_gs;

// ---------------- degree + slot reservation (g_packed must be 0 on entry) ----
__global__ void edge_accum_kernel(const int* __restrict__ dst,
                                  const float* __restrict__ ew) {
    int e = blockIdx.x * blockDim.x + threadIdx.x;
    if (e >= EE) return;
    int d = dst[e];
    unsigned int wfix = (unsigned int)(fabsf(ew[e]) * FPS + 0.5f);
    unsigned long long pk = (1ull << 32) | (unsigned long long)wfix;
    unsigned long long old = atomicAdd(&g_packed[d], pk);
    g_pos[e] = (int)(old >> 32);
}

// ---------------- block-level scan of counts ----------------
__global__ void scan_block_kernel() {
    __shared__ int sh[1024];
    int tid = threadIdx.x;
    int i = blockIdx.x * 1024 + tid;
    int v = (i < NN) ? (int)(g_packed[i] >> 32) : 0;
    sh[tid] = v;
    __syncthreads();
    #pragma unroll
    for (int off = 1; off < 1024; off <<= 1) {
        int t = (tid >= off) ? sh[tid - off] : 0;
        __syncthreads();
        sh[tid] += t;
        __syncthreads();
    }
    if (i < NN) g_rowst[i] = sh[tid] - v;
    if (tid == 1023) g_bsum[blockIdx.x] = sh[1023];
}

// ---------------- finalize offsets: inline bsum scan + dinv + state reset ----
__global__ void add_offsets_kernel() {          // 128 threads per block
    __shared__ int sh[128];
    __shared__ int pre[128];
    int t = threadIdx.x;
    int v = (t < NBLK) ? g_bsum[t] : 0;
    sh[t] = v;
    __syncthreads();
    #pragma unroll
    for (int off = 1; off < 128; off <<= 1) {
        int tmp = (t >= off) ? sh[t - off] : 0;
        __syncthreads();
        sh[t] += tmp;
        __syncthreads();
    }
    pre[t] = sh[t] - v;                          // exclusive block offsets
    __syncthreads();

    int i = blockIdx.x * blockDim.x + t;
    if (i >= NN) return;
    unsigned long long pk = g_packed[i];
    g_packed[i] = 0ull;                          // reset for next replay
    int cnt = (int)(pk >> 32);
    float deg = (float)(unsigned int)(pk & 0xffffffffull) * (1.0f / FPS) + 1.0f;
    g_rowst[i] += pre[i >> 10];
    g_cnt_e[i] = cnt;
    g_dinv[i]  = rsqrtf(deg);
}

// ---------------- scatter edges into CSR (streaming + 1 random 8B store) ----
__global__ void scatter_kernel(const int* __restrict__ src,
                               const int* __restrict__ dst,
                               const float* __restrict__ ew) {
    int e = blockIdx.x * blockDim.x + threadIdx.x;
    if (e >= EE) return;
    int s = src[e], d = dst[e];
    int pos = g_rowst[d] + g_pos[e];
    unsigned int wbits = __float_as_uint(fabsf(ew[e]));
    g_csr[pos] = ((unsigned long long)wbits << 32) | (unsigned int)s;
}

// ---------------- post-GEMM dinv row scale (layer 0 only; overlaps scatter) --
__global__ void scale_h_kernel() {
    int i = blockIdx.x * blockDim.x + threadIdx.x;   // uint2 (4 halfs) index
    if (i >= NN * 16) return;
    int node = i >> 4;
    float dv = g_dinv[node];
    uint2 u = *((const uint2*)g_bufH + i);
    float2 f0 = __half22float2(*reinterpret_cast<__half2*>(&u.x));
    float2 f1 = __half22float2(*reinterpret_cast<__half2*>(&u.y));
    __half2 lo = __floats2half2_rn(f0.x * dv, f0.y * dv);
    __half2 hi = __floats2half2_rn(f1.x * dv, f1.y * dv);
    uint2 o;
    o.x = *(unsigned int*)&lo;
    o.y = *(unsigned int*)&hi;
    *((uint2*)g_bufH + i) = o;
}

// ---------------- tensor-core GEMM: Yh = (X @ W) [* dinv[row]], fp16/fp32 acc
// 64x64 tile, 8 warps (4 row-blocks x 2 N-halves). Conflict-free padded strides.
template <int DIN, typename TIN, bool DODINV>
__global__ void __launch_bounds__(256) gemm_mma_kernel(const TIN* __restrict__ X,
                                                       const float* __restrict__ W,
                                                       __half* __restrict__ Yh) {
    constexpr int KP  = (DIN + 15) & ~15;     // 112 or 64
    constexpr int XS  = KP + 8;               // A smem stride (halfs); XS*2 % 16 == 0
    constexpr int WS  = 72;                   // B smem stride (halfs)
    constexpr int STS = 68;                   // staging stride (floats)
    constexpr int XB  = 64 * XS * 2;

    extern __shared__ __align__(16) char sm[];
    __half* Xs = (__half*)sm;
    __half* Ws = (__half*)(sm + XB);
    float*  St = (float*)sm;                  // overlaid after mma completes

    const int t    = threadIdx.x;
    const int warp = t >> 5;
    const int rw   = warp & 3;                // row block (16 rows)
    const int nh   = warp >> 2;               // N half (32 cols)
    const int base = blockIdx.x * 64;

    if constexpr (sizeof(TIN) == 4) {
        constexpr int KP4 = KP / 4;
        for (int i = t; i < 64 * KP4; i += 256) {
            int n = i / KP4;
            int k = (i - n * KP4) << 2;
            __half2 h0 = __floats2half2_rn(0.f, 0.f), h1 = h0;
            int nn = base + n;
            if (nn < NN && k + 3 < DIN) {
                float4 v = *(const float4*)((const float*)X + (size_t)nn * DIN + k);
                h0 = __floats2half2_rn(v.x, v.y);
                h1 = __floats2half2_rn(v.z, v.w);
            }
            *(__half2*)&Xs[n * XS + k]     = h0;
            *(__half2*)&Xs[n * XS + k + 2] = h1;
        }
    } else {
        constexpr int KP8 = KP / 8;
        for (int i = t; i < 64 * KP8; i += 256) {
            int n = i / KP8;
            int k = (i - n * KP8) << 3;
            uint4 u = make_uint4(0u, 0u, 0u, 0u);
            int nn = base + n;
            if (nn < NN)
                u = *(const uint4*)((const __half*)X + (size_t)nn * DIN + k);
            *(uint4*)&Xs[n * XS + k] = u;
        }
    }
    for (int i = t; i < KP * 16; i += 256) {
        int k = i >> 4;
        int c = (i & 15) << 2;
        __half2 h0 = __floats2half2_rn(0.f, 0.f), h1 = h0;
        if (k < DIN) {
            float4 w = *(const float4*)(W + (size_t)k * 64 + c);
            h0 = __floats2half2_rn(w.x, w.y);
            h1 = __floats2half2_rn(w.z, w.w);
        }
        *(__half2*)&Ws[k * WS + c]     = h0;
        *(__half2*)&Ws[k * WS + c + 2] = h1;
    }
    __syncthreads();

    wmma::fragment<wmma::accumulator, 16, 16, 16, float> acc[2];
    #pragma unroll
    for (int nb = 0; nb < 2; nb++) wmma::fill_fragment(acc[nb], 0.f);

    #pragma unroll
    for (int k = 0; k < KP; k += 16) {
        wmma::fragment<wmma::matrix_a, 16, 16, 16, __half, wmma::row_major> a;
        wmma::load_matrix_sync(a, Xs + rw * 16 * XS + k, XS);
        #pragma unroll
        for (int nb = 0; nb < 2; nb++) {
            wmma::fragment<wmma::matrix_b, 16, 16, 16, __half, wmma::row_major> bf;
            wmma::load_matrix_sync(bf, Ws + k * WS + (nh * 2 + nb) * 16, WS);
            wmma::mma_sync(acc[nb], a, bf, acc[nb]);
        }
    }
    __syncthreads();

    #pragma unroll
    for (int nb = 0; nb < 2; nb++)
        wmma::store_matrix_sync(St + rw * 16 * STS + (nh * 2 + nb) * 16, acc[nb],
                                STS, wmma::mem_row_major);
    __syncthreads();

    for (int i = t; i < 64 * 16; i += 256) {
        int n = i >> 4;
        int q = (i & 15) << 2;
        int nn = base + n;
        if (nn < NN) {
            float4 f = *(const float4*)&St[n * STS + q];
            float dv = DODINV ? g_dinv[nn] : 1.0f;
            __half2 lo = __floats2half2_rn(f.x * dv, f.y * dv);
            __half2 hi = __floats2half2_rn(f.z * dv, f.w * dv);
            uint2 u;
            u.x = *(unsigned int*)&lo;
            u.y = *(unsigned int*)&hi;
            *(uint2*)(Yh + (size_t)nn * 64 + q) = u;
        }
    }
}

// ---------------- fused CSR gather-reduce + BN + ReLU (+ pooling) ----------------
// half-warp (16 lanes) per dst node; lane owns 4 channels; TWO independent
// edge streams per node (front half / back half) processed concurrently so one
// stream's L2 wait overlaps the other's issue -> 2x in-flight gathers/thread.
__device__ __forceinline__ void acc_half4(float4& a, float w, uint2 u) {
    float2 f0 = __half22float2(*reinterpret_cast<__half2*>(&u.x));
    float2 f1 = __half22float2(*reinterpret_cast<__half2*>(&u.y));
    a.x = fmaf(w, f0.x, a.x); a.y = fmaf(w, f0.y, a.y);
    a.z = fmaf(w, f1.x, a.z); a.w = fmaf(w, f1.y, a.w);
}

template <bool LAST>
__global__ void __launch_bounds__(256) prop_fused_kernel(
                                  const __half* __restrict__ H,
                                  const float* __restrict__ b,
                                  const float* __restrict__ g,
                                  const float* __restrict__ bt,
                                  const float* __restrict__ rm,
                                  const float* __restrict__ rv,
                                  const int* __restrict__ batch,
                                  __half* __restrict__ out) {
    const int warp  = blockIdx.x * (blockDim.x >> 5) + (threadIdx.x >> 5);
    const int lane  = threadIdx.x & 31;
    const int half  = lane >> 4;
    const int sub   = lane & 15;
    const int node  = (warp << 1) + half;
    if (node >= NN) return;
    const int ch = sub << 2;

    const int s0  = g_rowst[node];
    const int cnt = g_cnt_e[node];
    const int s1  = s0 + cnt;
    const int mid = s0 + (cnt >> 1);

    float4 a0 = {0,0,0,0}, a1 = {0,0,0,0};   // stream A accums
    float4 a2 = {0,0,0,0}, a3 = {0,0,0,0};   // stream B accums

    const uint2* csr = (const uint2*)g_csr;
    int ka = s0, kb = mid;

    // fused dual-stream main loop: 4 gathers per stream in flight, chains independent
    while (ka + 4 <= mid && kb + 4 <= s1) {
        uint2 cA0 = __ldg(csr + ka);
        uint2 cA1 = __ldg(csr + ka + 1);
        uint2 cA2 = __ldg(csr + ka + 2);
        uint2 cA3 = __ldg(csr + ka + 3);
        uint2 cB0 = __ldg(csr + kb);
        uint2 cB1 = __ldg(csr + kb + 1);
        uint2 cB2 = __ldg(csr + kb + 2);
        uint2 cB3 = __ldg(csr + kb + 3);
        uint2 uA0 = *(const uint2*)(H + (size_t)cA0.x * 64 + ch);
        uint2 uA1 = *(const uint2*)(H + (size_t)cA1.x * 64 + ch);
        uint2 uA2 = *(const uint2*)(H + (size_t)cA2.x * 64 + ch);
        uint2 uA3 = *(const uint2*)(H + (size_t)cA3.x * 64 + ch);
        uint2 uB0 = *(const uint2*)(H + (size_t)cB0.x * 64 + ch);
        uint2 uB1 = *(const uint2*)(H + (size_t)cB1.x * 64 + ch);
        uint2 uB2 = *(const uint2*)(H + (size_t)cB2.x * 64 + ch);
        uint2 uB3 = *(const uint2*)(H + (size_t)cB3.x * 64 + ch);
        acc_half4(a0, __uint_as_float(cA0.y), uA0);
        acc_half4(a1, __uint_as_float(cA1.y), uA1);
        acc_half4(a0, __uint_as_float(cA2.y), uA2);
        acc_half4(a1, __uint_as_float(cA3.y), uA3);
        acc_half4(a2, __uint_as_float(cB0.y), uB0);
        acc_half4(a3, __uint_as_float(cB1.y), uB1);
        acc_half4(a2, __uint_as_float(cB2.y), uB2);
        acc_half4(a3, __uint_as_float(cB3.y), uB3);
        ka += 4; kb += 4;
    }
    // drain stream A
    for (; ka + 4 <= mid; ka += 4) {
        uint2 c0 = __ldg(csr + ka);
        uint2 c1 = __ldg(csr + ka + 1);
        uint2 c2 = __ldg(csr + ka + 2);
        uint2 c3 = __ldg(csr + ka + 3);
        uint2 u0 = *(const uint2*)(H + (size_t)c0.x * 64 + ch);
        uint2 u1 = *(const uint2*)(H + (size_t)c1.x * 64 + ch);
        uint2 u2 = *(const uint2*)(H + (size_t)c2.x * 64 + ch);
        uint2 u3 = *(const uint2*)(H + (size_t)c3.x * 64 + ch);
        acc_half4(a0, __uint_as_float(c0.y), u0);
        acc_half4(a1, __uint_as_float(c1.y), u1);
        acc_half4(a0, __uint_as_float(c2.y), u2);
        acc_half4(a1, __uint_as_float(c3.y), u3);
    }
    for (; ka < mid; ka++) {
        uint2 c0 = __ldg(csr + ka);
        uint2 u0 = *(const uint2*)(H + (size_t)c0.x * 64 + ch);
        acc_half4(a0, __uint_as_float(c0.y), u0);
    }
    // drain stream B
    for (; kb + 4 <= s1; kb += 4) {
        uint2 c0 = __ldg(csr + kb);
        uint2 c1 = __ldg(csr + kb + 1);
        uint2 c2 = __ldg(csr + kb + 2);
        uint2 c3 = __ldg(csr + kb + 3);
        uint2 u0 = *(const uint2*)(H + (size_t)c0.x * 64 + ch);
        uint2 u1 = *(const uint2*)(H + (size_t)c1.x * 64 + ch);
        uint2 u2 = *(const uint2*)(H + (size_t)c2.x * 64 + ch);
        uint2 u3 = *(const uint2*)(H + (size_t)c3.x * 64 + ch);
        acc_half4(a2, __uint_as_float(c0.y), u0);
        acc_half4(a3, __uint_as_float(c1.y), u1);
        acc_half4(a2, __uint_as_float(c2.y), u2);
        acc_half4(a3, __uint_as_float(c3.y), u3);
    }
    for (; kb < s1; kb++) {
        uint2 c0 = __ldg(csr + kb);
        uint2 u0 = *(const uint2*)(H + (size_t)c0.x * 64 + ch);
        acc_half4(a2, __uint_as_float(c0.y), u0);
    }

    // combine: self term Ht[d] has implicit weight 1
    const float dv = g_dinv[node];
    uint2 uh = *(const uint2*)(H + (size_t)node * 64 + ch);
    float2 h0 = __half22float2(*reinterpret_cast<__half2*>(&uh.x));
    float2 h1 = __half22float2(*reinterpret_cast<__half2*>(&uh.y));
    float4 bb  = *(const float4*)(b  + ch);
    float4 gg  = *(const float4*)(g  + ch);
    float4 btv = *(const float4*)(bt + ch);
    float4 rmv = *(const float4*)(rm + ch);
    float4 rvv = *(const float4*)(rv + ch);

    float sx = fmaf((a0.x + a2.x) + h0.x, dv, bb.x);
    float sy = fmaf((a0.y + a2.y) + h0.y, dv, bb.y);
    float sz = fmaf((a0.z + a2.z) + h1.x, dv, bb.z);
    float sw = fmaf((a0.w + a2.w) + h1.y, dv, bb.w);
    sx += (a1.x + a3.x) * dv;
    sy += (a1.y + a3.y) * dv;
    sz += (a1.z + a3.z) * dv;
    sw += (a1.w + a3.w) * dv;

    sx = fmaxf((sx - rmv.x) * (gg.x * rsqrtf(rvv.x + EPS)) + btv.x, 0.f);
    sy = fmaxf((sy - rmv.y) * (gg.y * rsqrtf(rvv.y + EPS)) + btv.y, 0.f);
    sz = fmaxf((sz - rmv.z) * (gg.z * rsqrtf(rvv.z + EPS)) + btv.z, 0.f);
    sw = fmaxf((sw - rmv.w) * (gg.w * rsqrtf(rvv.w + EPS)) + btv.w, 0.f);

    if (LAST) {
        int gr = __ldg(batch + node);
        float4 r = make_float4(sx, sy, sz, sw);
        atomicAdd((float4*)(g_pool + gr * 64 + ch), r);
        if (sub == 0) atomicAdd(&g_gcnt[gr], 1.0f);
    } else {
        uint2 o;
        __half2 lo = __floats2half2_rn(sx, sy);
        __half2 hi = __floats2half2_rn(sz, sw);
        o.x = *(unsigned int*)&lo;
        o.y = *(unsigned int*)&hi;
        *(uint2*)(out + (size_t)node * 64 + ch) = o;
    }
}

// ---------------- final output (+ pool reset for next replay) ----------------
__global__ void out_kernel(float* __restrict__ out) {
    int gr = blockIdx.x;        // 0..31
    int c  = threadIdx.x;       // 0..127
    float s  = g_pool[gr * 64 + (c & 63)];
    float cc = fmaxf(g_gcnt[gr], 1.0f);
    out[gr * 128 + c] = (c < 64) ? s / cc : s;
    __syncthreads();
    if (c < 64) g_pool[gr * 64 + c] = 0.f;
    if (c == 64) g_gcnt[gr] = 0.f;
}

// ---------------- launch ----------------
extern "C" void kernel_launch(void* const* d_in, const int* in_sizes, int n_in,
                              void* d_out, int out_size) {
    const float* x     = (const float*)d_in[0];
    const int*   ei    = (const int*)  d_in[1];
    const float* ew    = (const float*)d_in[2];
    const int*   batch = (const int*)  d_in[3];
    const int*   src   = ei;
    const int*   dst   = ei + EE;
    float* out = (float*)d_out;

    const float *Wl[3], *bl[3], *gl[3], *btl[3], *rml[3], *rvl[3];
    for (int l = 0; l < 3; l++) {
        Wl[l]  = (const float*)d_in[4 + 6 * l + 0];
        bl[l]  = (const float*)d_in[4 + 6 * l + 1];
        gl[l]  = (const float*)d_in[4 + 6 * l + 2];
        btl[l] = (const float*)d_in[4 + 6 * l + 3];
        rml[l] = (const float*)d_in[4 + 6 * l + 4];
        rvl[l] = (const float*)d_in[4 + 6 * l + 5];
    }

    __half *bufH, *bufB;
    cudaGetSymbolAddress((void**)&bufH, g_bufH);
    cudaGetSymbolAddress((void**)&bufB, g_bufB);

    // dynamic smem sizes (64-row tiles)
    const int STB = 64 * 68 * 4;                          // 17408
    int SB0 = 64 * 120 * 2 + 112 * 72 * 2;                // 31488
    if (SB0 < STB) SB0 = STB;
    int SB1 = 64 * 72 * 2 + 64 * 72 * 2;                  // 18432
    if (SB1 < STB) SB1 = STB;
    cudaFuncSetAttribute((const void*)gemm_mma_kernel<INC, float, false>,
                         cudaFuncAttributeMaxDynamicSharedMemorySize, SB0);
    cudaFuncSetAttribute((const void*)gemm_mma_kernel<HC, __half, true>,
                         cudaFuncAttributeMaxDynamicSharedMemorySize, SB1);

    const int T = 256;
    const int eGrid = (EE + T - 1) / T;
    const int gemmGrid = (NN + 63) / 64;
    const int propGrid = (NN / 2 + 7) / 8;   // 8 warps/block, 2 nodes/warp

    // ---- forked graph: branch A (side stream) = gemm0 (+dinv scale after join)
    //      branch B (main stream) = CSR build; join before prop0
    cudaEventRecord(g_gs.evRoot, 0);                       // fork point
    cudaStreamWaitEvent(g_gs.s1, g_gs.evRoot, 0);
    gemm_mma_kernel<INC, float, false><<<gemmGrid, 256, SB0, g_gs.s1>>>(x, Wl[0], bufH);

    edge_accum_kernel<<<eGrid, T>>>(dst, ew);              // main
    scan_block_kernel<<<NBLK, 1024>>>();
    add_offsets_kernel<<<(NN + 127) / 128, 128>>>();
    cudaEventRecord(g_gs.evOff, 0);                        // dinv ready
    cudaStreamWaitEvent(g_gs.s1, g_gs.evOff, 0);
    scale_h_kernel<<<(NN * 16 + T - 1) / T, T, 0, g_gs.s1>>>();   // bufH *= dinv
    cudaEventRecord(g_gs.evGemm, g_gs.s1);

    scatter_kernel<<<eGrid, T>>>(src, dst, ew);            // main, overlaps branch A

    cudaStreamWaitEvent(0, g_gs.evGemm, 0);                // join
    prop_fused_kernel<false><<<propGrid, 256>>>(bufH, bl[0], gl[0], btl[0],
                                                rml[0], rvl[0], batch, bufB);
    gemm_mma_kernel<HC, __half, true><<<gemmGrid, 256, SB1>>>(bufB, Wl[1], bufH);
    prop_fused_kernel<false><<<propGrid, 256>>>(bufH, bl[1], gl[1], btl[1],
                                                rml[1], rvl[1], batch, bufB);
    gemm_mma_kernel<HC, __half, true><<<gemmGrid, 256, SB1>>>(bufB, Wl[2], bufH);
    prop_fused_kernel<true><<<propGrid, 256>>>(bufH, bl[2], gl[2], btl[2],
                                               rml[2], rvl[2], batch, bufB);

    out_kernel<<<GG, 128>>>(out);
}

// round 17
// speedup vs baseline: 1.0717x; 1.0717x over previous
#include <cuda_runtime.h>
#include <cuda_fp16.h>
#include <mma.h>
#include <math.h>

using namespace nvcuda;

#define NN 100000
#define EE 1600000
#define GG 32
#define INC 100
#define HC 64
#define EPS 1e-5f
#define NBLK 98            // ceil(NN/1024)
#define FPS 1048576.0f     // 2^20 fixed-point scale for degree

// ---------------- scratch (zero-initialized at module load; kernels that
// consume one-shot state re-zero it afterwards so graph replays are exact) ----
__device__ unsigned long long g_packed[NN];  // (count<<32) | fixedpoint(sum|w|)
__device__ float  g_dinv [NN];
__device__ int    g_cnt_e[NN];
__device__ int    g_rowst[NN];
__device__ int    g_bsum [128];
__device__ int    g_pos  [EE];
__device__ unsigned long long g_csr[EE];     // packed (|ew| bits << 32) | src
__device__ __half g_bufH [(size_t)NN * HC];  // GEMM output (dinv-scaled before prop)
__device__ __half g_bufB [(size_t)NN * HC];  // prop output (next GEMM input)
__device__ float  g_pool [GG * HC];
__device__ float  g_gcnt [GG];

// streams/events for forked graph capture — created once at load time,
// before any harness memory checkpoint; reused every call (no per-call churn)
static struct GraphStreams {
    cudaStream_t s1;
    cudaEvent_t evRoot, evOff, evGemm;
    GraphStreams() {
        cudaStreamCreateWithFlags(&s1, cudaStreamNonBlocking);
        cudaEventCreateWithFlags(&evRoot, cudaEventDisableTiming);
        cudaEventCreateWithFlags(&evOff,  cudaEventDisableTiming);
        cudaEventCreateWithFlags(&evGemm, cudaEventDisableTiming);
    }
} g_gs;

// ---------------- degree + slot reservation (g_packed must be 0 on entry) ----
__global__ void edge_accum_kernel(const int* __restrict__ dst,
                                  const float* __restrict__ ew) {
    int e = blockIdx.x * blockDim.x + threadIdx.x;
    if (e >= EE) return;
    int d = dst[e];
    unsigned int wfix = (unsigned int)(fabsf(ew[e]) * FPS + 0.5f);
    unsigned long long pk = (1ull << 32) | (unsigned long long)wfix;
    unsigned long long old = atomicAdd(&g_packed[d], pk);
    g_pos[e] = (int)(old >> 32);
}

// ---------------- block-level scan of counts ----------------
__global__ void scan_block_kernel() {
    __shared__ int sh[1024];
    int tid = threadIdx.x;
    int i = blockIdx.x * 1024 + tid;
    int v = (i < NN) ? (int)(g_packed[i] >> 32) : 0;
    sh[tid] = v;
    __syncthreads();
    #pragma unroll
    for (int off = 1; off < 1024; off <<= 1) {
        int t = (tid >= off) ? sh[tid - off] : 0;
        __syncthreads();
        sh[tid] += t;
        __syncthreads();
    }
    if (i < NN) g_rowst[i] = sh[tid] - v;
    if (tid == 1023) g_bsum[blockIdx.x] = sh[1023];
}

// ---------------- finalize offsets: inline bsum scan + dinv + state reset ----
__global__ void add_offsets_kernel() {          // 128 threads per block
    __shared__ int sh[128];
    __shared__ int pre[128];
    int t = threadIdx.x;
    int v = (t < NBLK) ? g_bsum[t] : 0;
    sh[t] = v;
    __syncthreads();
    #pragma unroll
    for (int off = 1; off < 128; off <<= 1) {
        int tmp = (t >= off) ? sh[t - off] : 0;
        __syncthreads();
        sh[t] += tmp;
        __syncthreads();
    }
    pre[t] = sh[t] - v;                          // exclusive block offsets
    __syncthreads();

    int i = blockIdx.x * blockDim.x + t;
    if (i >= NN) return;
    unsigned long long pk = g_packed[i];
    g_packed[i] = 0ull;                          // reset for next replay
    int cnt = (int)(pk >> 32);
    float deg = (float)(unsigned int)(pk & 0xffffffffull) * (1.0f / FPS) + 1.0f;
    g_rowst[i] += pre[i >> 10];
    g_cnt_e[i] = cnt;
    g_dinv[i]  = rsqrtf(deg);
}

// ---------------- scatter edges into CSR (streaming + 1 random 8B store) ----
__global__ void scatter_kernel(const int* __restrict__ src,
                               const int* __restrict__ dst,
                               const float* __restrict__ ew) {
    int e = blockIdx.x * blockDim.x + threadIdx.x;
    if (e >= EE) return;
    int s = src[e], d = dst[e];
    int pos = g_rowst[d] + g_pos[e];
    unsigned int wbits = __float_as_uint(fabsf(ew[e]));
    g_csr[pos] = ((unsigned long long)wbits << 32) | (unsigned int)s;
}

// ---------------- post-GEMM dinv row scale (layer 0 only; overlaps scatter) --
__global__ void scale_h_kernel() {
    int i = blockIdx.x * blockDim.x + threadIdx.x;   // uint2 (4 halfs) index
    if (i >= NN * 16) return;
    int node = i >> 4;
    float dv = g_dinv[node];
    uint2 u = *((const uint2*)g_bufH + i);
    float2 f0 = __half22float2(*reinterpret_cast<__half2*>(&u.x));
    float2 f1 = __half22float2(*reinterpret_cast<__half2*>(&u.y));
    __half2 lo = __floats2half2_rn(f0.x * dv, f0.y * dv);
    __half2 hi = __floats2half2_rn(f1.x * dv, f1.y * dv);
    uint2 o;
    o.x = *(unsigned int*)&lo;
    o.y = *(unsigned int*)&hi;
    *((uint2*)g_bufH + i) = o;
}

// ---------------- tensor-core GEMM: Yh = (X @ W) [* dinv[row]], fp16/fp32 acc
// 64x64 tile, 8 warps (4 row-blocks x 2 N-halves). Conflict-free padded strides.
template <int DIN, typename TIN, bool DODINV>
__global__ void __launch_bounds__(256) gemm_mma_kernel(const TIN* __restrict__ X,
                                                       const float* __restrict__ W,
                                                       __half* __restrict__ Yh) {
    constexpr int KP  = (DIN + 15) & ~15;     // 112 or 64
    constexpr int XS  = KP + 8;               // A smem stride (halfs); XS*2 % 16 == 0
    constexpr int WS  = 72;                   // B smem stride (halfs)
    constexpr int STS = 68;                   // staging stride (floats)
    constexpr int XB  = 64 * XS * 2;

    extern __shared__ __align__(16) char sm[];
    __half* Xs = (__half*)sm;
    __half* Ws = (__half*)(sm + XB);
    float*  St = (float*)sm;                  // overlaid after mma completes

    const int t    = threadIdx.x;
    const int warp = t >> 5;
    const int rw   = warp & 3;                // row block (16 rows)
    const int nh   = warp >> 2;               // N half (32 cols)
    const int base = blockIdx.x * 64;

    if constexpr (sizeof(TIN) == 4) {
        constexpr int KP4 = KP / 4;
        for (int i = t; i < 64 * KP4; i += 256) {
            int n = i / KP4;
            int k = (i - n * KP4) << 2;
            __half2 h0 = __floats2half2_rn(0.f, 0.f), h1 = h0;
            int nn = base + n;
            if (nn < NN && k + 3 < DIN) {
                float4 v = *(const float4*)((const float*)X + (size_t)nn * DIN + k);
                h0 = __floats2half2_rn(v.x, v.y);
                h1 = __floats2half2_rn(v.z, v.w);
            }
            *(__half2*)&Xs[n * XS + k]     = h0;
            *(__half2*)&Xs[n * XS + k + 2] = h1;
        }
    } else {
        constexpr int KP8 = KP / 8;
        for (int i = t; i < 64 * KP8; i += 256) {
            int n = i / KP8;
            int k = (i - n * KP8) << 3;
            uint4 u = make_uint4(0u, 0u, 0u, 0u);
            int nn = base + n;
            if (nn < NN)
                u = *(const uint4*)((const __half*)X + (size_t)nn * DIN + k);
            *(uint4*)&Xs[n * XS + k] = u;
        }
    }
    for (int i = t; i < KP * 16; i += 256) {
        int k = i >> 4;
        int c = (i & 15) << 2;
        __half2 h0 = __floats2half2_rn(0.f, 0.f), h1 = h0;
        if (k < DIN) {
            float4 w = *(const float4*)(W + (size_t)k * 64 + c);
            h0 = __floats2half2_rn(w.x, w.y);
            h1 = __floats2half2_rn(w.z, w.w);
        }
        *(__half2*)&Ws[k * WS + c]     = h0;
        *(__half2*)&Ws[k * WS + c + 2] = h1;
    }
    __syncthreads();

    wmma::fragment<wmma::accumulator, 16, 16, 16, float> acc[2];
    #pragma unroll
    for (int nb = 0; nb < 2; nb++) wmma::fill_fragment(acc[nb], 0.f);

    #pragma unroll
    for (int k = 0; k < KP; k += 16) {
        wmma::fragment<wmma::matrix_a, 16, 16, 16, __half, wmma::row_major> a;
        wmma::load_matrix_sync(a, Xs + rw * 16 * XS + k, XS);
        #pragma unroll
        for (int nb = 0; nb < 2; nb++) {
            wmma::fragment<wmma::matrix_b, 16, 16, 16, __half, wmma::row_major> bf;
            wmma::load_matrix_sync(bf, Ws + k * WS + (nh * 2 + nb) * 16, WS);
            wmma::mma_sync(acc[nb], a, bf, acc[nb]);
        }
    }
    __syncthreads();

    #pragma unroll
    for (int nb = 0; nb < 2; nb++)
        wmma::store_matrix_sync(St + rw * 16 * STS + (nh * 2 + nb) * 16, acc[nb],
                                STS, wmma::mem_row_major);
    __syncthreads();

    for (int i = t; i < 64 * 16; i += 256) {
        int n = i >> 4;
        int q = (i & 15) << 2;
        int nn = base + n;
        if (nn < NN) {
            float4 f = *(const float4*)&St[n * STS + q];
            float dv = DODINV ? g_dinv[nn] : 1.0f;
            __half2 lo = __floats2half2_rn(f.x * dv, f.y * dv);
            __half2 hi = __floats2half2_rn(f.z * dv, f.w * dv);
            uint2 u;
            u.x = *(unsigned int*)&lo;
            u.y = *(unsigned int*)&hi;
            *(uint2*)(Yh + (size_t)nn * 64 + q) = u;
        }
    }
}

// ---------------- fused CSR gather-reduce + BN + ReLU (+ pooling) ----------------
// half-warp (16 lanes) per dst node; lane owns 4 channels; shuffle-free, unroll 8.
// __launch_bounds__(256, 6): cap regs ~42 -> 6 blocks/SM (75% occ) to raise the
// number of resident warps hiding the L2 gather latency.
__device__ __forceinline__ void acc_half4(float4& a, float w, uint2 u) {
    float2 f0 = __half22float2(*reinterpret_cast<__half2*>(&u.x));
    float2 f1 = __half22float2(*reinterpret_cast<__half2*>(&u.y));
    a.x = fmaf(w, f0.x, a.x); a.y = fmaf(w, f0.y, a.y);
    a.z = fmaf(w, f1.x, a.z); a.w = fmaf(w, f1.y, a.w);
}

template <bool LAST>
__global__ void __launch_bounds__(256, 6) prop_fused_kernel(
                                  const __half* __restrict__ H,
                                  const float* __restrict__ b,
                                  const float* __restrict__ g,
                                  const float* __restrict__ bt,
                                  const float* __restrict__ rm,
                                  const float* __restrict__ rv,
                                  const int* __restrict__ batch,
                                  __half* __restrict__ out) {
    const int warp  = blockIdx.x * (blockDim.x >> 5) + (threadIdx.x >> 5);
    const int lane  = threadIdx.x & 31;
    const int half  = lane >> 4;
    const int sub   = lane & 15;
    const int node  = (warp << 1) + half;
    if (node >= NN) return;
    const int ch = sub << 2;

    const int s0 = g_rowst[node];
    const int s1 = s0 + g_cnt_e[node];

    float4 a0 = {0,0,0,0}, a1 = {0,0,0,0}, a2 = {0,0,0,0}, a3 = {0,0,0,0};

    const uint2* csr = (const uint2*)g_csr;
    int k = s0;
    for (; k + 8 <= s1; k += 8) {        // 8 independent csr+row gathers in flight
        uint2 c0 = __ldg(csr + k);
        uint2 c1 = __ldg(csr + k + 1);
        uint2 c2 = __ldg(csr + k + 2);
        uint2 c3 = __ldg(csr + k + 3);
        uint2 c4 = __ldg(csr + k + 4);
        uint2 c5 = __ldg(csr + k + 5);
        uint2 c6 = __ldg(csr + k + 6);
        uint2 c7 = __ldg(csr + k + 7);
        uint2 u0 = *(const uint2*)(H + (size_t)c0.x * 64 + ch);
        uint2 u1 = *(const uint2*)(H + (size_t)c1.x * 64 + ch);
        uint2 u2 = *(const uint2*)(H + (size_t)c2.x * 64 + ch);
        uint2 u3 = *(const uint2*)(H + (size_t)c3.x * 64 + ch);
        uint2 u4 = *(const uint2*)(H + (size_t)c4.x * 64 + ch);
        uint2 u5 = *(const uint2*)(H + (size_t)c5.x * 64 + ch);
        uint2 u6 = *(const uint2*)(H + (size_t)c6.x * 64 + ch);
        uint2 u7 = *(const uint2*)(H + (size_t)c7.x * 64 + ch);
        acc_half4(a0, __uint_as_float(c0.y), u0);
        acc_half4(a1, __uint_as_float(c1.y), u1);
        acc_half4(a2, __uint_as_float(c2.y), u2);
        acc_half4(a3, __uint_as_float(c3.y), u3);
        acc_half4(a0, __uint_as_float(c4.y), u4);
        acc_half4(a1, __uint_as_float(c5.y), u5);
        acc_half4(a2, __uint_as_float(c6.y), u6);
        acc_half4(a3, __uint_as_float(c7.y), u7);
    }
    for (; k + 4 <= s1; k += 4) {
        uint2 c0 = __ldg(csr + k);
        uint2 c1 = __ldg(csr + k + 1);
        uint2 c2 = __ldg(csr + k + 2);
        uint2 c3 = __ldg(csr + k + 3);
        uint2 u0 = *(const uint2*)(H + (size_t)c0.x * 64 + ch);
        uint2 u1 = *(const uint2*)(H + (size_t)c1.x * 64 + ch);
        uint2 u2 = *(const uint2*)(H + (size_t)c2.x * 64 + ch);
        uint2 u3 = *(const uint2*)(H + (size_t)c3.x * 64 + ch);
        acc_half4(a0, __uint_as_float(c0.y), u0);
        acc_half4(a1, __uint_as_float(c1.y), u1);
        acc_half4(a2, __uint_as_float(c2.y), u2);
        acc_half4(a3, __uint_as_float(c3.y), u3);
    }
    for (; k < s1; k++) {
        uint2 c0 = __ldg(csr + k);
        uint2 u0 = *(const uint2*)(H + (size_t)c0.x * 64 + ch);
        acc_half4(a0, __uint_as_float(c0.y), u0);
    }

    // combine: self term Ht[d] has implicit weight 1
    const float dv = g_dinv[node];
    uint2 uh = *(const uint2*)(H + (size_t)node * 64 + ch);
    float2 h0 = __half22float2(*reinterpret_cast<__half2*>(&uh.x));
    float2 h1 = __half22float2(*reinterpret_cast<__half2*>(&uh.y));
    float4 bb  = *(const float4*)(b  + ch);
    float4 gg  = *(const float4*)(g  + ch);
    float4 btv = *(const float4*)(bt + ch);
    float4 rmv = *(const float4*)(rm + ch);
    float4 rvv = *(const float4*)(rv + ch);

    float sx = fmaf(((a0.x + a1.x) + (a2.x + a3.x)) + h0.x, dv, bb.x);
    float sy = fmaf(((a0.y + a1.y) + (a2.y + a3.y)) + h0.y, dv, bb.y);
    float sz = fmaf(((a0.z + a1.z) + (a2.z + a3.z)) + h1.x, dv, bb.z);
    float sw = fmaf(((a0.w + a1.w) + (a2.w + a3.w)) + h1.y, dv, bb.w);

    sx = fmaxf((sx - rmv.x) * (gg.x * rsqrtf(rvv.x + EPS)) + btv.x, 0.f);
    sy = fmaxf((sy - rmv.y) * (gg.y * rsqrtf(rvv.y + EPS)) + btv.y, 0.f);
    sz = fmaxf((sz - rmv.z) * (gg.z * rsqrtf(rvv.z + EPS)) + btv.z, 0.f);
    sw = fmaxf((sw - rmv.w) * (gg.w * rsqrtf(rvv.w + EPS)) + btv.w, 0.f);

    if (LAST) {
        int gr = __ldg(batch + node);
        float4 r = make_float4(sx, sy, sz, sw);
        atomicAdd((float4*)(g_pool + gr * 64 + ch), r);
        if (sub == 0) atomicAdd(&g_gcnt[gr], 1.0f);
    } else {
        uint2 o;
        __half2 lo = __floats2half2_rn(sx, sy);
        __half2 hi = __floats2half2_rn(sz, sw);
        o.x = *(unsigned int*)&lo;
        o.y = *(unsigned int*)&hi;
        *(uint2*)(out + (size_t)node * 64 + ch) = o;
    }
}

// ---------------- final output (+ pool reset for next replay) ----------------
__global__ void out_kernel(float* __restrict__ out) {
    int gr = blockIdx.x;        // 0..31
    int c  = threadIdx.x;       // 0..127
    float s  = g_pool[gr * 64 + (c & 63)];
    float cc = fmaxf(g_gcnt[gr], 1.0f);
    out[gr * 128 + c] = (c < 64) ? s / cc : s;
    __syncthreads();
    if (c < 64) g_pool[gr * 64 + c] = 0.f;
    if (c == 64) g_gcnt[gr] = 0.f;
}

// ---------------- launch ----------------
extern "C" void kernel_launch(void* const* d_in, const int* in_sizes, int n_in,
                              void* d_out, int out_size) {
    const float* x     = (const float*)d_in[0];
    const int*   ei    = (const int*)  d_in[1];
    const float* ew    = (const float*)d_in[2];
    const int*   batch = (const int*)  d_in[3];
    const int*   src   = ei;
    const int*   dst   = ei + EE;
    float* out = (float*)d_out;

    const float *Wl[3], *bl[3], *gl[3], *btl[3], *rml[3], *rvl[3];
    for (int l = 0; l < 3; l++) {
        Wl[l]  = (const float*)d_in[4 + 6 * l + 0];
        bl[l]  = (const float*)d_in[4 + 6 * l + 1];
        gl[l]  = (const float*)d_in[4 + 6 * l + 2];
        btl[l] = (const float*)d_in[4 + 6 * l + 3];
        rml[l] = (const float*)d_in[4 + 6 * l + 4];
        rvl[l] = (const float*)d_in[4 + 6 * l + 5];
    }

    __half *bufH, *bufB;
    cudaGetSymbolAddress((void**)&bufH, g_bufH);
    cudaGetSymbolAddress((void**)&bufB, g_bufB);

    // dynamic smem sizes (64-row tiles)
    const int STB = 64 * 68 * 4;                          // 17408
    int SB0 = 64 * 120 * 2 + 112 * 72 * 2;                // 31488
    if (SB0 < STB) SB0 = STB;
    int SB1 = 64 * 72 * 2 + 64 * 72 * 2;                  // 18432
    if (SB1 < STB) SB1 = STB;
    cudaFuncSetAttribute((const void*)gemm_mma_kernel<INC, float, false>,
                         cudaFuncAttributeMaxDynamicSharedMemorySize, SB0);
    cudaFuncSetAttribute((const void*)gemm_mma_kernel<HC, __half, true>,
                         cudaFuncAttributeMaxDynamicSharedMemorySize, SB1);

    const int T = 256;
    const int eGrid = (EE + T - 1) / T;
    const int gemmGrid = (NN + 63) / 64;
    const int propGrid = (NN / 2 + 7) / 8;   // 8 warps/block, 2 nodes/warp

    // ---- forked graph: branch A (side stream) = gemm0 (+dinv scale after join)
    //      branch B (main stream) = CSR build; join before prop0
    cudaEventRecord(g_gs.evRoot, 0);                       // fork point
    cudaStreamWaitEvent(g_gs.s1, g_gs.evRoot, 0);
    gemm_mma_kernel<INC, float, false><<<gemmGrid, 256, SB0, g_gs.s1>>>(x, Wl[0], bufH);

    edge_accum_kernel<<<eGrid, T>>>(dst, ew);              // main
    scan_block_kernel<<<NBLK, 1024>>>();
    add_offsets_kernel<<<(NN + 127) / 128, 128>>>();
    cudaEventRecord(g_gs.evOff, 0);                        // dinv ready
    cudaStreamWaitEvent(g_gs.s1, g_gs.evOff, 0);
    scale_h_kernel<<<(NN * 16 + T - 1) / T, T, 0, g_gs.s1>>>();   // bufH *= dinv
    cudaEventRecord(g_gs.evGemm, g_gs.s1);

    scatter_kernel<<<eGrid, T>>>(src, dst, ew);            // main, overlaps branch A

    cudaStreamWaitEvent(0, g_gs.evGemm, 0);                // join
    prop_fused_kernel<false><<<propGrid, 256>>>(bufH, bl[0], gl[0], btl[0],
                                                rml[0], rvl[0], batch, bufB);
    gemm_mma_kernel<HC, __half, true><<<gemmGrid, 256, SB1>>>(bufB, Wl[1], bufH);
    prop_fused_kernel<false><<<propGrid, 256>>>(bufH, bl[1], gl[1], btl[1],
                                                rml[1], rvl[1], batch, bufB);
    gemm_mma_kernel<HC, __half, true><<<gemmGrid, 256, SB1>>>(bufB, Wl[2], bufH);
    prop_fused_kernel<true><<<propGrid, 256>>>(bufH, bl[2], gl[2], btl[2],
                                               rml[2], rvl[2], batch, bufB);

    out_kernel<<<GG, 128>>>(out);
}